// round 5
// baseline (speedup 1.0000x reference)
#include <cuda_runtime.h>
#include <cuda_bf16.h>
#include <cstdint>

#define N_NODES 50000
#define N_EDGES 600000
#define FEAT    128
#define N_CLS   40
#define SCAN_BLOCKS 196   // ceil(50000/256)

// ---------------- scratch (no allocations allowed) ----------------
__device__ float g_dinv[N_NODES];
__device__ int   g_degi[N_NODES];
__device__ int   g_rowptr[N_NODES];
__device__ int   g_cursor[N_NODES];
__device__ int   g_esrc[N_EDGES];
__device__ int   g_bsum[SCAN_BLOCKS];
__device__ float g_h1[N_NODES * FEAT];
__device__ float g_h2[N_NODES * FEAT];
__device__ float g_h3[N_NODES * FEAT];
// pre-split weights: [layer][mat(Wl,Wr)] -> hi[16384], lo[16384] bf16 dense row-major
__device__ __nv_bfloat16 g_wsplit[3 * 2 * 2 * 16384];

// ---------------- CSR build ----------------
__global__ void zero_degi() {
    int i = blockIdx.x * blockDim.x + threadIdx.x;
    if (i < N_NODES) g_degi[i] = 0;
}

__global__ void deg_count_i(const int* __restrict__ dst) {
    int e = blockIdx.x * blockDim.x + threadIdx.x;
    if (e < N_EDGES) atomicAdd(&g_degi[dst[e]], 1);
}

__global__ void scan_part() {
    __shared__ int red[256];
    int i = blockIdx.x * 256 + threadIdx.x;
    int v = (i < N_NODES) ? g_degi[i] : 0;
    red[threadIdx.x] = v;
    __syncthreads();
    for (int s = 128; s > 0; s >>= 1) {
        if (threadIdx.x < s) red[threadIdx.x] += red[threadIdx.x + s];
        __syncthreads();
    }
    if (threadIdx.x == 0) g_bsum[blockIdx.x] = red[0];
}

__global__ void scan_top() {
    int t = threadIdx.x;
    int lane = t & 31, wid = t >> 5;
    int v = (t < SCAN_BLOCKS) ? g_bsum[t] : 0;
    int inc = v;
#pragma unroll
    for (int d = 1; d < 32; d <<= 1) {
        int u = __shfl_up_sync(0xffffffffu, inc, d);
        if (lane >= d) inc += u;
    }
    __shared__ int wsum[8];
    if (lane == 31) wsum[wid] = inc;
    __syncthreads();
    if (wid == 0 && lane < 8) {
        int w = wsum[lane];
        int winc = w;
#pragma unroll
        for (int d = 1; d < 8; d <<= 1) {
            int u = __shfl_up_sync(0xffu, winc, d);
            if (lane >= d) winc += u;
        }
        wsum[lane] = winc - w;
    }
    __syncthreads();
    if (t < SCAN_BLOCKS) g_bsum[t] = inc - v + wsum[wid];
}

__global__ void scan_final() {
    int t = threadIdx.x;
    int lane = t & 31, wid = t >> 5;
    int i = blockIdx.x * 256 + t;
    int v = (i < N_NODES) ? g_degi[i] : 0;
    int inc = v;
#pragma unroll
    for (int d = 1; d < 32; d <<= 1) {
        int u = __shfl_up_sync(0xffffffffu, inc, d);
        if (lane >= d) inc += u;
    }
    __shared__ int wsum[8];
    if (lane == 31) wsum[wid] = inc;
    __syncthreads();
    if (wid == 0 && lane < 8) {
        int w = wsum[lane];
        int winc = w;
#pragma unroll
        for (int d = 1; d < 8; d <<= 1) {
            int u = __shfl_up_sync(0xffu, winc, d);
            if (lane >= d) winc += u;
        }
        wsum[lane] = winc - w;
    }
    __syncthreads();
    if (i < N_NODES) {
        int excl = inc - v + wsum[wid] + g_bsum[blockIdx.x];
        g_rowptr[i] = excl;
        g_cursor[i] = excl;
        g_dinv[i]   = 1.0f / fmaxf((float)v, 1.0f);
    }
}

__global__ void bucket_edges(const int* __restrict__ src, const int* __restrict__ dst) {
    int e = blockIdx.x * blockDim.x + threadIdx.x;
    if (e < N_EDGES) {
        int d = dst[e];
        int pos = atomicAdd(&g_cursor[d], 1);
        g_esrc[pos] = src[e];
    }
}

// ---------------- weight pre-split (once) ----------------
__global__ void prep_weights(const float* __restrict__ Wl1, const float* __restrict__ Wr1,
                             const float* __restrict__ Wl2, const float* __restrict__ Wr2,
                             const float* __restrict__ Wl3, const float* __restrict__ Wr3) {
    int idx = blockIdx.x * blockDim.x + threadIdx.x;
    if (idx >= 3 * 2 * 16384) return;
    int lm = idx / 16384;           // layer*2 + mat
    int e  = idx % 16384;
    const float* W;
    switch (lm) {
        case 0: W = Wl1; break;
        case 1: W = Wr1; break;
        case 2: W = Wl2; break;
        case 3: W = Wr2; break;
        case 4: W = Wl3; break;
        default: W = Wr3; break;
    }
    float f = __ldg(W + e);
    __nv_bfloat16 h = __float2bfloat16(f);
    __nv_bfloat16 l = __float2bfloat16(f - __bfloat162float(h));
    __nv_bfloat16* base = g_wsplit + (size_t)lm * 32768;
    base[e]         = h;
    base[16384 + e] = l;
}

// ---------------- mma.sync bf16 + ldmatrix (baseline PTX) ----------------
__device__ __forceinline__ void mma_bf16(float* c, const uint32_t* a, uint32_t b0, uint32_t b1) {
    asm volatile(
        "mma.sync.aligned.m16n8k16.row.col.f32.bf16.bf16.f32 "
        "{%0,%1,%2,%3}, {%4,%5,%6,%7}, {%8,%9}, {%0,%1,%2,%3};"
        : "+f"(c[0]), "+f"(c[1]), "+f"(c[2]), "+f"(c[3])
        : "r"(a[0]), "r"(a[1]), "r"(a[2]), "r"(a[3]), "r"(b0), "r"(b1));
}

#define LDMX4(R, addr) \
    asm volatile("ldmatrix.sync.aligned.m8n8.x4.shared.b16 {%0,%1,%2,%3}, [%4];" \
        : "=r"((R)[0]), "=r"((R)[1]), "=r"((R)[2]), "=r"((R)[3]) : "r"(addr))

__device__ __forceinline__ uint32_t smem_u32(const void* p) {
    uint32_t a;
    asm("{ .reg .u64 t; cvta.to.shared.u64 t, %1; cvt.u32.u64 %0, t; }" : "=r"(a) : "l"(p));
    return a;
}

#define LDS_STRIDE 136   // 272B rows (17 x 16B, odd -> ldmatrix conflict-free)

__device__ __forceinline__ void split2(float f0, float f1, uint32_t& hw, uint32_t& lw) {
    __nv_bfloat16 h0 = __float2bfloat16(f0);
    __nv_bfloat16 h1 = __float2bfloat16(f1);
    __nv_bfloat16 l0 = __float2bfloat16(f0 - __bfloat162float(h0));
    __nv_bfloat16 l1 = __float2bfloat16(f1 - __bfloat162float(h1));
    hw = ((uint32_t)__bfloat16_as_ushort(h1) << 16) | __bfloat16_as_ushort(h0);
    lw = ((uint32_t)__bfloat16_as_ushort(l1) << 16) | __bfloat16_as_ushort(l0);
}

// ---------------- fused SAGE layer: gather + dual GEMM + relu (+res) ----------------
// BM=64, BN=128, K=128. 8 warps: (wid&1)->M half, (wid>>1)->N quarter; warp tile 32x32.
// smem: sAh/sAl 64 rows + sWh/sWl 128 rows = 104448 B -> 2 blocks/SM.
#define SMEM_FUSED ((2 * 64 + 2 * 128) * LDS_STRIDE * 2)

__global__ __launch_bounds__(256, 2)
void sage_fused(const float* __restrict__ Xin,
                const __nv_bfloat16* __restrict__ wsplit,  // layer base: Wl hi,lo then Wr hi,lo
                const float* __restrict__ bl,
                const float* __restrict__ res,             // may be null
                float* __restrict__ out) {
    extern __shared__ __align__(16) char smraw[];
    __nv_bfloat16* sAh = reinterpret_cast<__nv_bfloat16*>(smraw);
    __nv_bfloat16* sAl = sAh + 64 * LDS_STRIDE;
    __nv_bfloat16* sWh = sAl + 64 * LDS_STRIDE;
    __nv_bfloat16* sWl = sWh + 128 * LDS_STRIDE;
    __shared__ float s_bl[128];

    const int tid  = threadIdx.x;
    const int wid  = tid >> 5;
    const int lane = tid & 31;
    const int g    = lane >> 2;
    const int tg   = lane & 3;
    const int m0   = blockIdx.x * 64;
    const int m0w  = (wid & 1) * 32;
    const int n0w  = (wid >> 1) * 32;

    if (tid < 128) s_bl[tid] = __ldg(bl + tid);

    const uint32_t aoff = (uint32_t)(((lane & 15) * LDS_STRIDE + (lane >> 4) * 8) * 2);
    const uint32_t boff = (uint32_t)((((lane & 7) + ((lane >> 4) << 3)) * LDS_STRIDE
                                      + ((lane >> 3) & 1) * 8) * 2);
    const uint32_t uAh = smem_u32(sAh), uAl = smem_u32(sAl);
    const uint32_t uWh = smem_u32(sWh), uWl = smem_u32(sWl);

    // ---- gather phase: warp w aggregates nodes m0 + w*8 .. +7 into sA ----
    {
#pragma unroll 1
        for (int i = 0; i < 8; i++) {
            int r = wid * 8 + i;
            int m = m0 + r;
            float4 acc = make_float4(0.f, 0.f, 0.f, 0.f);
            if (m < N_NODES) {
                int start = __ldg(g_rowptr + m);
                int deg   = __ldg(g_degi + m);
                int j = 0;
                for (; j + 4 <= deg; j += 4) {
                    int s0 = __ldg(g_esrc + start + j);
                    int s1 = __ldg(g_esrc + start + j + 1);
                    int s2 = __ldg(g_esrc + start + j + 2);
                    int s3 = __ldg(g_esrc + start + j + 3);
                    float4 v0 = __ldg(reinterpret_cast<const float4*>(Xin + (size_t)s0 * FEAT) + lane);
                    float4 v1 = __ldg(reinterpret_cast<const float4*>(Xin + (size_t)s1 * FEAT) + lane);
                    float4 v2 = __ldg(reinterpret_cast<const float4*>(Xin + (size_t)s2 * FEAT) + lane);
                    float4 v3 = __ldg(reinterpret_cast<const float4*>(Xin + (size_t)s3 * FEAT) + lane);
                    acc.x += v0.x + v1.x + v2.x + v3.x;
                    acc.y += v0.y + v1.y + v2.y + v3.y;
                    acc.z += v0.z + v1.z + v2.z + v3.z;
                    acc.w += v0.w + v1.w + v2.w + v3.w;
                }
                for (; j < deg; j++) {
                    int s = __ldg(g_esrc + start + j);
                    float4 v = __ldg(reinterpret_cast<const float4*>(Xin + (size_t)s * FEAT) + lane);
                    acc.x += v.x; acc.y += v.y; acc.z += v.z; acc.w += v.w;
                }
                float di = __ldg(g_dinv + m);
                acc.x *= di; acc.y *= di; acc.z *= di; acc.w *= di;
            }
            uint32_t h0, l0, h1, l1;
            split2(acc.x, acc.y, h0, l0);
            split2(acc.z, acc.w, h1, l1);
            int eoff = r * LDS_STRIDE + lane * 4;
            *reinterpret_cast<uint2*>(sAh + eoff) = make_uint2(h0, h1);
            *reinterpret_cast<uint2*>(sAl + eoff) = make_uint2(l0, l1);
        }
    }
    // stage Wl (pre-split bf16 copy)
    {
        const __nv_bfloat16* whi = wsplit;          // Wl hi
        const __nv_bfloat16* wlo = wsplit + 16384;  // Wl lo
        for (int it = tid; it < 2048; it += 256) {
            int r = it >> 4, c = it & 15;
            int so = r * 128 + c * 8, eo = r * LDS_STRIDE + c * 8;
            *reinterpret_cast<uint4*>(sWh + eo) = __ldg(reinterpret_cast<const uint4*>(whi + so));
            *reinterpret_cast<uint4*>(sWl + eo) = __ldg(reinterpret_cast<const uint4*>(wlo + so));
        }
    }
    __syncthreads();

    float acc[2][4][4];
#pragma unroll
    for (int mt = 0; mt < 2; mt++)
#pragma unroll
        for (int nt = 0; nt < 4; nt++)
#pragma unroll
            for (int q = 0; q < 4; q++) acc[mt][nt][q] = 0.f;

    // ---- pass 1: aggm @ Wl^T ----
#pragma unroll
    for (int kk = 0; kk < 8; kk++) {
        const uint32_t kB = kk * 32;
        uint32_t ah[2][4], al[2][4], bh[2][4], blo[2][4];
#pragma unroll
        for (int mt = 0; mt < 2; mt++) {
            uint32_t rb = (uint32_t)((m0w + mt * 16) * LDS_STRIDE * 2) + kB + aoff;
            LDMX4(ah[mt], uAh + rb);
            LDMX4(al[mt], uAl + rb);
        }
#pragma unroll
        for (int p = 0; p < 2; p++) {
            uint32_t rb = (uint32_t)((n0w + p * 16) * LDS_STRIDE * 2) + kB + boff;
            LDMX4(bh[p],  uWh + rb);
            LDMX4(blo[p], uWl + rb);
        }
#pragma unroll
        for (int mt = 0; mt < 2; mt++)
#pragma unroll
            for (int nt = 0; nt < 4; nt++) {
                int p = nt >> 1, s = (nt & 1) * 2;
                mma_bf16(acc[mt][nt], ah[mt], bh[p][s], bh[p][s + 1]);
                mma_bf16(acc[mt][nt], al[mt], bh[p][s], bh[p][s + 1]);
                mma_bf16(acc[mt][nt], ah[mt], blo[p][s], blo[p][s + 1]);
            }
    }
    __syncthreads();

    // ---- restage: A <- X rows (split on the fly), W <- Wr (pre-split copy) ----
    for (int it = tid; it < 1024; it += 256) {
        int r = it >> 4, c = it & 15;
        int m = m0 + r;
        float4 v0 = make_float4(0.f, 0.f, 0.f, 0.f), v1 = v0;
        if (m < N_NODES) {
            const float4* gp = reinterpret_cast<const float4*>(Xin + (size_t)m * FEAT + c * 8);
            v0 = __ldg(gp);
            v1 = __ldg(gp + 1);
        }
        uint32_t hw[4], lw[4];
        split2(v0.x, v0.y, hw[0], lw[0]);
        split2(v0.z, v0.w, hw[1], lw[1]);
        split2(v1.x, v1.y, hw[2], lw[2]);
        split2(v1.z, v1.w, hw[3], lw[3]);
        int eo = r * LDS_STRIDE + c * 8;
        *reinterpret_cast<uint4*>(sAh + eo) = make_uint4(hw[0], hw[1], hw[2], hw[3]);
        *reinterpret_cast<uint4*>(sAl + eo) = make_uint4(lw[0], lw[1], lw[2], lw[3]);
    }
    {
        const __nv_bfloat16* whi = wsplit + 32768;          // Wr hi
        const __nv_bfloat16* wlo = wsplit + 32768 + 16384;  // Wr lo
        for (int it = tid; it < 2048; it += 256) {
            int r = it >> 4, c = it & 15;
            int so = r * 128 + c * 8, eo = r * LDS_STRIDE + c * 8;
            *reinterpret_cast<uint4*>(sWh + eo) = __ldg(reinterpret_cast<const uint4*>(whi + so));
            *reinterpret_cast<uint4*>(sWl + eo) = __ldg(reinterpret_cast<const uint4*>(wlo + so));
        }
    }
    __syncthreads();

    // ---- pass 2: x @ Wr^T (accumulate) ----
#pragma unroll
    for (int kk = 0; kk < 8; kk++) {
        const uint32_t kB = kk * 32;
        uint32_t ah[2][4], al[2][4], bh[2][4], blo[2][4];
#pragma unroll
        for (int mt = 0; mt < 2; mt++) {
            uint32_t rb = (uint32_t)((m0w + mt * 16) * LDS_STRIDE * 2) + kB + aoff;
            LDMX4(ah[mt], uAh + rb);
            LDMX4(al[mt], uAl + rb);
        }
#pragma unroll
        for (int p = 0; p < 2; p++) {
            uint32_t rb = (uint32_t)((n0w + p * 16) * LDS_STRIDE * 2) + kB + boff;
            LDMX4(bh[p],  uWh + rb);
            LDMX4(blo[p], uWl + rb);
        }
#pragma unroll
        for (int mt = 0; mt < 2; mt++)
#pragma unroll
            for (int nt = 0; nt < 4; nt++) {
                int p = nt >> 1, s = (nt & 1) * 2;
                mma_bf16(acc[mt][nt], ah[mt], bh[p][s], bh[p][s + 1]);
                mma_bf16(acc[mt][nt], al[mt], bh[p][s], bh[p][s + 1]);
                mma_bf16(acc[mt][nt], ah[mt], blo[p][s], blo[p][s + 1]);
            }
    }

    // ---- epilogue: bias + relu (+ residual) ----
#pragma unroll
    for (int mt = 0; mt < 2; mt++) {
#pragma unroll
        for (int half = 0; half < 2; half++) {
            int m = m0 + m0w + mt * 16 + g + half * 8;
            if (m < N_NODES) {
#pragma unroll
                for (int nt = 0; nt < 4; nt++) {
                    int n = n0w + nt * 8 + tg * 2;
                    float2 v;
                    v.x = fmaxf(acc[mt][nt][half * 2 + 0] + s_bl[n], 0.f);
                    v.y = fmaxf(acc[mt][nt][half * 2 + 1] + s_bl[n + 1], 0.f);
                    if (res) {
                        float2 rv = *reinterpret_cast<const float2*>(res + (size_t)m * FEAT + n);
                        v.x += rv.x; v.y += rv.y;
                    }
                    *reinterpret_cast<float2*>(out + (size_t)m * FEAT + n) = v;
                }
            }
        }
    }
}

// ---------------- classifier (fp32, small) ----------------
#define PAD 129
#define SMEM_CLS ((128 * PAD + 40 * PAD) * (int)sizeof(float))

__global__ __launch_bounds__(256)
void classifier_k(const float* __restrict__ X,
                  const float* __restrict__ Wc,
                  const float* __restrict__ bc,
                  float* __restrict__ out) {
    extern __shared__ float smf[];
    float* sX = smf;
    float* sW = smf + 128 * PAD;

    const int tid  = threadIdx.x;
    const int warp = tid >> 5;
    const int lane = tid & 31;
    const int tx   = tid & 7;
    const int ty   = tid >> 3;
    const int m0   = blockIdx.x * 128;

    for (int r = warp; r < 128; r += 8) {
        int m = m0 + r;
        float4 v = make_float4(0.f, 0.f, 0.f, 0.f);
        if (m < N_NODES)
            v = __ldg(reinterpret_cast<const float4*>(X + (size_t)m * FEAT) + lane);
        float* row = sX + r * PAD + lane * 4;
        row[0] = v.x; row[1] = v.y; row[2] = v.z; row[3] = v.w;
    }
    for (int n = warp; n < N_CLS; n += 8) {
        float4 v = __ldg(reinterpret_cast<const float4*>(Wc + (size_t)n * FEAT) + lane);
        float* row = sW + n * PAD + lane * 4;
        row[0] = v.x; row[1] = v.y; row[2] = v.z; row[3] = v.w;
    }
    __syncthreads();

    float acc[4][5];
#pragma unroll
    for (int r = 0; r < 4; r++)
#pragma unroll
        for (int c = 0; c < 5; c++) acc[r][c] = 0.f;

#pragma unroll 4
    for (int k = 0; k < 128; k++) {
        float a[4], w[5];
#pragma unroll
        for (int r = 0; r < 4; r++) a[r] = sX[(ty * 4 + r) * PAD + k];
#pragma unroll
        for (int c = 0; c < 5; c++) w[c] = sW[(tx + 8 * c) * PAD + k];
#pragma unroll
        for (int r = 0; r < 4; r++)
#pragma unroll
            for (int c = 0; c < 5; c++)
                acc[r][c] = fmaf(a[r], w[c], acc[r][c]);
    }

#pragma unroll
    for (int r = 0; r < 4; r++) {
        int m = m0 + ty * 4 + r;
        if (m < N_NODES) {
#pragma unroll
            for (int c = 0; c < 5; c++) {
                int n = tx + 8 * c;
                out[(size_t)m * N_CLS + n] = acc[r][c] + __ldg(bc + n);
            }
        }
    }
}

// ---------------- launch ----------------
extern "C" void kernel_launch(void* const* d_in, const int* in_sizes, int n_in,
                              void* d_out, int out_size) {
    const float* x   = (const float*)d_in[0];
    const int*   ei  = (const int*)d_in[1];
    const float* Wl1 = (const float*)d_in[2];
    const float* bl1 = (const float*)d_in[3];
    const float* Wr1 = (const float*)d_in[4];
    const float* Wl2 = (const float*)d_in[5];
    const float* bl2 = (const float*)d_in[6];
    const float* Wr2 = (const float*)d_in[7];
    const float* Wl3 = (const float*)d_in[8];
    const float* bl3 = (const float*)d_in[9];
    const float* Wr3 = (const float*)d_in[10];
    const float* Wc  = (const float*)d_in[11];
    const float* bc  = (const float*)d_in[12];
    float* out = (float*)d_out;

    const int* src = ei;
    const int* dst = ei + N_EDGES;

    float *p_h1, *p_h2, *p_h3;
    __nv_bfloat16* p_ws;
    cudaGetSymbolAddress((void**)&p_h1, g_h1);
    cudaGetSymbolAddress((void**)&p_h2, g_h2);
    cudaGetSymbolAddress((void**)&p_h3, g_h3);
    cudaGetSymbolAddress((void**)&p_ws, g_wsplit);

    cudaFuncSetAttribute(sage_fused,   cudaFuncAttributeMaxDynamicSharedMemorySize, SMEM_FUSED);
    cudaFuncSetAttribute(classifier_k, cudaFuncAttributeMaxDynamicSharedMemorySize, SMEM_CLS);

    const int edge_blocks  = (N_EDGES + 255) / 256;
    const int fused_blocks = (N_NODES + 63) / 64;
    const int cls_blocks   = (N_NODES + 127) / 128;
    const size_t WSTRIDE = 2 * 2 * 16384;   // bf16 per layer

    // weight prep + CSR build (once)
    prep_weights<<<(3 * 2 * 16384 + 255) / 256, 256>>>(Wl1, Wr1, Wl2, Wr2, Wl3, Wr3);
    zero_degi<<<(N_NODES + 255) / 256, 256>>>();
    deg_count_i<<<edge_blocks, 256>>>(dst);
    scan_part<<<SCAN_BLOCKS, 256>>>();
    scan_top<<<1, 256>>>();
    scan_final<<<SCAN_BLOCKS, 256>>>();
    bucket_edges<<<edge_blocks, 256>>>(src, dst);

    // 3 fused layers
    sage_fused<<<fused_blocks, 256, SMEM_FUSED>>>(x,    p_ws + 0 * WSTRIDE, bl1, nullptr, p_h1);
    sage_fused<<<fused_blocks, 256, SMEM_FUSED>>>(p_h1, p_ws + 1 * WSTRIDE, bl2, nullptr, p_h2);
    sage_fused<<<fused_blocks, 256, SMEM_FUSED>>>(p_h2, p_ws + 2 * WSTRIDE, bl3, p_h2,    p_h3);

    // classifier
    classifier_k<<<cls_blocks, 256, SMEM_CLS>>>(p_h3, Wc, bc, out);
}

// round 6
// speedup vs baseline: 1.2326x; 1.2326x over previous
#include <cuda_runtime.h>
#include <cuda_bf16.h>
#include <cstdint>

#define N_NODES 50000
#define N_EDGES 600000
#define FEAT    128
#define N_CLS   40
#define SCAN_BLOCKS 196   // ceil(50000/256)

// ---------------- scratch (no allocations allowed) ----------------
__device__ float g_dinv[N_NODES];
__device__ int   g_degi[N_NODES];
__device__ int   g_rowptr[N_NODES];
__device__ int   g_cursor[N_NODES];
__device__ int   g_esrc[N_EDGES];
__device__ int   g_bsum[SCAN_BLOCKS];
__device__ float g_agg[N_NODES * FEAT];
__device__ float g_h1[N_NODES * FEAT];
__device__ float g_h2[N_NODES * FEAT];
__device__ float g_h3[N_NODES * FEAT];
// pre-split weights: [layer][mat(Wl,Wr)] -> hi[16384], lo[16384] bf16 dense row-major
__device__ __nv_bfloat16 g_wsplit[3 * 2 * 2 * 16384];

// ---------------- CSR build ----------------
__global__ void zero_degi() {
    int i = blockIdx.x * blockDim.x + threadIdx.x;
    if (i < N_NODES) g_degi[i] = 0;
}

__global__ void deg_count_i(const int* __restrict__ dst) {
    int e = blockIdx.x * blockDim.x + threadIdx.x;
    if (e < N_EDGES) atomicAdd(&g_degi[dst[e]], 1);
}

__global__ void scan_part() {
    __shared__ int red[256];
    int i = blockIdx.x * 256 + threadIdx.x;
    int v = (i < N_NODES) ? g_degi[i] : 0;
    red[threadIdx.x] = v;
    __syncthreads();
    for (int s = 128; s > 0; s >>= 1) {
        if (threadIdx.x < s) red[threadIdx.x] += red[threadIdx.x + s];
        __syncthreads();
    }
    if (threadIdx.x == 0) g_bsum[blockIdx.x] = red[0];
}

__global__ void scan_top() {
    int t = threadIdx.x;
    int lane = t & 31, wid = t >> 5;
    int v = (t < SCAN_BLOCKS) ? g_bsum[t] : 0;
    int inc = v;
#pragma unroll
    for (int d = 1; d < 32; d <<= 1) {
        int u = __shfl_up_sync(0xffffffffu, inc, d);
        if (lane >= d) inc += u;
    }
    __shared__ int wsum[8];
    if (lane == 31) wsum[wid] = inc;
    __syncthreads();
    if (wid == 0 && lane < 8) {
        int w = wsum[lane];
        int winc = w;
#pragma unroll
        for (int d = 1; d < 8; d <<= 1) {
            int u = __shfl_up_sync(0xffu, winc, d);
            if (lane >= d) winc += u;
        }
        wsum[lane] = winc - w;
    }
    __syncthreads();
    if (t < SCAN_BLOCKS) g_bsum[t] = inc - v + wsum[wid];
}

__global__ void scan_final() {
    int t = threadIdx.x;
    int lane = t & 31, wid = t >> 5;
    int i = blockIdx.x * 256 + t;
    int v = (i < N_NODES) ? g_degi[i] : 0;
    int inc = v;
#pragma unroll
    for (int d = 1; d < 32; d <<= 1) {
        int u = __shfl_up_sync(0xffffffffu, inc, d);
        if (lane >= d) inc += u;
    }
    __shared__ int wsum[8];
    if (lane == 31) wsum[wid] = inc;
    __syncthreads();
    if (wid == 0 && lane < 8) {
        int w = wsum[lane];
        int winc = w;
#pragma unroll
        for (int d = 1; d < 8; d <<= 1) {
            int u = __shfl_up_sync(0xffu, winc, d);
            if (lane >= d) winc += u;
        }
        wsum[lane] = winc - w;
    }
    __syncthreads();
    if (i < N_NODES) {
        int excl = inc - v + wsum[wid] + g_bsum[blockIdx.x];
        g_rowptr[i] = excl;
        g_cursor[i] = excl;
        g_dinv[i]   = 1.0f / fmaxf((float)v, 1.0f);
    }
}

__global__ void bucket_edges(const int* __restrict__ src, const int* __restrict__ dst) {
    int e = blockIdx.x * blockDim.x + threadIdx.x;
    if (e < N_EDGES) {
        int d = dst[e];
        int pos = atomicAdd(&g_cursor[d], 1);
        g_esrc[pos] = src[e];
    }
}

// ---------------- weight pre-split (once) ----------------
__global__ void prep_weights(const float* __restrict__ Wl1, const float* __restrict__ Wr1,
                             const float* __restrict__ Wl2, const float* __restrict__ Wr2,
                             const float* __restrict__ Wl3, const float* __restrict__ Wr3) {
    int idx = blockIdx.x * blockDim.x + threadIdx.x;
    if (idx >= 3 * 2 * 16384) return;
    int lm = idx / 16384;           // layer*2 + mat
    int e  = idx % 16384;
    const float* W;
    switch (lm) {
        case 0: W = Wl1; break;
        case 1: W = Wr1; break;
        case 2: W = Wl2; break;
        case 3: W = Wr2; break;
        case 4: W = Wl3; break;
        default: W = Wr3; break;
    }
    float f = __ldg(W + e);
    __nv_bfloat16 h = __float2bfloat16(f);
    __nv_bfloat16 l = __float2bfloat16(f - __bfloat162float(h));
    __nv_bfloat16* base = g_wsplit + (size_t)lm * 32768;
    base[e]         = h;
    base[16384 + e] = l;
}

// ---------------- CSR mean-gather: one warp per node ----------------
__global__ __launch_bounds__(256)
void gather_mean(const float* __restrict__ X) {
    int wid  = (blockIdx.x * blockDim.x + threadIdx.x) >> 5;
    int lane = threadIdx.x & 31;
    if (wid >= N_NODES) return;
    int start = g_rowptr[wid];
    int deg   = g_degi[wid];
    float4 acc = make_float4(0.f, 0.f, 0.f, 0.f);
    int j = 0;
    for (; j + 4 <= deg; j += 4) {
        int s0 = __ldg(g_esrc + start + j);
        int s1 = __ldg(g_esrc + start + j + 1);
        int s2 = __ldg(g_esrc + start + j + 2);
        int s3 = __ldg(g_esrc + start + j + 3);
        float4 v0 = __ldg(reinterpret_cast<const float4*>(X + (size_t)s0 * FEAT) + lane);
        float4 v1 = __ldg(reinterpret_cast<const float4*>(X + (size_t)s1 * FEAT) + lane);
        float4 v2 = __ldg(reinterpret_cast<const float4*>(X + (size_t)s2 * FEAT) + lane);
        float4 v3 = __ldg(reinterpret_cast<const float4*>(X + (size_t)s3 * FEAT) + lane);
        acc.x += v0.x + v1.x + v2.x + v3.x;
        acc.y += v0.y + v1.y + v2.y + v3.y;
        acc.z += v0.z + v1.z + v2.z + v3.z;
        acc.w += v0.w + v1.w + v2.w + v3.w;
    }
    for (; j < deg; j++) {
        int s = __ldg(g_esrc + start + j);
        float4 v = __ldg(reinterpret_cast<const float4*>(X + (size_t)s * FEAT) + lane);
        acc.x += v.x; acc.y += v.y; acc.z += v.z; acc.w += v.w;
    }
    float di = g_dinv[wid];
    acc.x *= di; acc.y *= di; acc.z *= di; acc.w *= di;
    reinterpret_cast<float4*>(g_agg + (size_t)wid * FEAT)[lane] = acc;
}

// ---------------- mma.sync bf16 + ldmatrix (baseline PTX) ----------------
__device__ __forceinline__ void mma_bf16(float* c, const uint32_t* a, uint32_t b0, uint32_t b1) {
    asm volatile(
        "mma.sync.aligned.m16n8k16.row.col.f32.bf16.bf16.f32 "
        "{%0,%1,%2,%3}, {%4,%5,%6,%7}, {%8,%9}, {%0,%1,%2,%3};"
        : "+f"(c[0]), "+f"(c[1]), "+f"(c[2]), "+f"(c[3])
        : "r"(a[0]), "r"(a[1]), "r"(a[2]), "r"(a[3]), "r"(b0), "r"(b1));
}

#define LDMX4(R, addr) \
    asm volatile("ldmatrix.sync.aligned.m8n8.x4.shared.b16 {%0,%1,%2,%3}, [%4];" \
        : "=r"((R)[0]), "=r"((R)[1]), "=r"((R)[2]), "=r"((R)[3]) : "r"(addr))

__device__ __forceinline__ uint32_t smem_u32(const void* p) {
    uint32_t a;
    asm("{ .reg .u64 t; cvta.to.shared.u64 t, %1; cvt.u32.u64 %0, t; }" : "=r"(a) : "l"(p));
    return a;
}

#define LDS_STRIDE 136   // 272B rows (17 x 16B, odd -> ldmatrix conflict-free)

__device__ __forceinline__ void split2(float f0, float f1, uint32_t& hw, uint32_t& lw) {
    __nv_bfloat16 h0 = __float2bfloat16(f0);
    __nv_bfloat16 h1 = __float2bfloat16(f1);
    __nv_bfloat16 l0 = __float2bfloat16(f0 - __bfloat162float(h0));
    __nv_bfloat16 l1 = __float2bfloat16(f1 - __bfloat162float(h1));
    hw = ((uint32_t)__bfloat16_as_ushort(h1) << 16) | __bfloat16_as_ushort(h0);
    lw = ((uint32_t)__bfloat16_as_ushort(l1) << 16) | __bfloat16_as_ushort(l0);
}

// ---------------- SAGE layer GEMM (BM=64, occupancy 2) ----------------
// out = relu( aggm @ Wl^T + x @ Wr^T + bl ) (+ res)   [aggm pre-scaled]
// 8 warps: (wid&1)->M half (32 rows), (wid>>1)->N quarter (32 cols).
#define SMEM_MMA ((2 * 64 + 2 * 128) * LDS_STRIDE * 2)   // 104448 B

__global__ __launch_bounds__(256, 2)
void sage_gemm_mma(const float* __restrict__ Ain, const float* __restrict__ Xin,
                   const __nv_bfloat16* __restrict__ wsplit,  // Wl hi,lo then Wr hi,lo
                   const float* __restrict__ bl,
                   const float* __restrict__ res, float* __restrict__ out) {
    extern __shared__ __align__(16) char smraw[];
    __nv_bfloat16* sAh = reinterpret_cast<__nv_bfloat16*>(smraw);
    __nv_bfloat16* sAl = sAh + 64 * LDS_STRIDE;
    __nv_bfloat16* sWh = sAl + 64 * LDS_STRIDE;
    __nv_bfloat16* sWl = sWh + 128 * LDS_STRIDE;
    __shared__ float s_bl[128];

    const int tid  = threadIdx.x;
    const int wid  = tid >> 5;
    const int lane = tid & 31;
    const int g    = lane >> 2;
    const int tg   = lane & 3;
    const int m0   = blockIdx.x * 64;
    const int m0w  = (wid & 1) * 32;
    const int n0w  = (wid >> 1) * 32;

    if (tid < 128) s_bl[tid] = __ldg(bl + tid);

    const uint32_t aoff = (uint32_t)(((lane & 15) * LDS_STRIDE + (lane >> 4) * 8) * 2);
    const uint32_t boff = (uint32_t)((((lane & 7) + ((lane >> 4) << 3)) * LDS_STRIDE
                                      + ((lane >> 3) & 1) * 8) * 2);
    const uint32_t uAh = smem_u32(sAh), uAl = smem_u32(sAl);
    const uint32_t uWh = smem_u32(sWh), uWl = smem_u32(sWl);

    float acc[2][4][4];
#pragma unroll
    for (int mt = 0; mt < 2; mt++)
#pragma unroll
        for (int nt = 0; nt < 4; nt++)
#pragma unroll
            for (int q = 0; q < 4; q++) acc[mt][nt][q] = 0.f;

    for (int pass = 0; pass < 2; pass++) {
        if (pass) __syncthreads();
        // stage A: 64 rows, fp32 -> split bf16
        {
            const float* A = pass ? Xin : Ain;
            for (int it = tid; it < 1024; it += 256) {
                int r = it >> 4, c = it & 15;
                int m = m0 + r;
                float4 v0 = make_float4(0.f, 0.f, 0.f, 0.f), v1 = v0;
                if (m < N_NODES) {
                    const float4* gp = reinterpret_cast<const float4*>(A + (size_t)m * FEAT + c * 8);
                    v0 = __ldg(gp);
                    v1 = __ldg(gp + 1);
                }
                uint32_t hw[4], lw[4];
                split2(v0.x, v0.y, hw[0], lw[0]);
                split2(v0.z, v0.w, hw[1], lw[1]);
                split2(v1.x, v1.y, hw[2], lw[2]);
                split2(v1.z, v1.w, hw[3], lw[3]);
                int eo = r * LDS_STRIDE + c * 8;
                *reinterpret_cast<uint4*>(sAh + eo) = make_uint4(hw[0], hw[1], hw[2], hw[3]);
                *reinterpret_cast<uint4*>(sAl + eo) = make_uint4(lw[0], lw[1], lw[2], lw[3]);
            }
        }
        // stage W: pre-split bf16 copy
        {
            const __nv_bfloat16* whi = wsplit + (pass ? 32768 : 0);
            const __nv_bfloat16* wlo = whi + 16384;
            for (int it = tid; it < 2048; it += 256) {
                int r = it >> 4, c = it & 15;
                int so = r * 128 + c * 8, eo = r * LDS_STRIDE + c * 8;
                *reinterpret_cast<uint4*>(sWh + eo) = __ldg(reinterpret_cast<const uint4*>(whi + so));
                *reinterpret_cast<uint4*>(sWl + eo) = __ldg(reinterpret_cast<const uint4*>(wlo + so));
            }
        }
        __syncthreads();

#pragma unroll
        for (int kk = 0; kk < 8; kk++) {
            const uint32_t kB = kk * 32;
            uint32_t ah[2][4], al[2][4], bh[2][4], blo[2][4];
#pragma unroll
            for (int mt = 0; mt < 2; mt++) {
                uint32_t rb = (uint32_t)((m0w + mt * 16) * LDS_STRIDE * 2) + kB + aoff;
                LDMX4(ah[mt], uAh + rb);
                LDMX4(al[mt], uAl + rb);
            }
#pragma unroll
            for (int p = 0; p < 2; p++) {
                uint32_t rb = (uint32_t)((n0w + p * 16) * LDS_STRIDE * 2) + kB + boff;
                LDMX4(bh[p],  uWh + rb);
                LDMX4(blo[p], uWl + rb);
            }
#pragma unroll
            for (int mt = 0; mt < 2; mt++)
#pragma unroll
                for (int nt = 0; nt < 4; nt++) {
                    int p = nt >> 1, s = (nt & 1) * 2;
                    mma_bf16(acc[mt][nt], ah[mt], bh[p][s], bh[p][s + 1]);
                    mma_bf16(acc[mt][nt], al[mt], bh[p][s], bh[p][s + 1]);
                    mma_bf16(acc[mt][nt], ah[mt], blo[p][s], blo[p][s + 1]);
                }
        }
    }

    // epilogue: bias + relu (+ residual)
#pragma unroll
    for (int mt = 0; mt < 2; mt++) {
#pragma unroll
        for (int half = 0; half < 2; half++) {
            int m = m0 + m0w + mt * 16 + g + half * 8;
            if (m < N_NODES) {
#pragma unroll
                for (int nt = 0; nt < 4; nt++) {
                    int n = n0w + nt * 8 + tg * 2;
                    float2 v;
                    v.x = fmaxf(acc[mt][nt][half * 2 + 0] + s_bl[n], 0.f);
                    v.y = fmaxf(acc[mt][nt][half * 2 + 1] + s_bl[n + 1], 0.f);
                    if (res) {
                        float2 rv = *reinterpret_cast<const float2*>(res + (size_t)m * FEAT + n);
                        v.x += rv.x; v.y += rv.y;
                    }
                    *reinterpret_cast<float2*>(out + (size_t)m * FEAT + n) = v;
                }
            }
        }
    }
}

// ---------------- classifier (fp32, small) ----------------
#define PAD 129
#define SMEM_CLS ((128 * PAD + 40 * PAD) * (int)sizeof(float))

__global__ __launch_bounds__(256)
void classifier_k(const float* __restrict__ X,
                  const float* __restrict__ Wc,
                  const float* __restrict__ bc,
                  float* __restrict__ out) {
    extern __shared__ float smf[];
    float* sX = smf;
    float* sW = smf + 128 * PAD;

    const int tid  = threadIdx.x;
    const int warp = tid >> 5;
    const int lane = tid & 31;
    const int tx   = tid & 7;
    const int ty   = tid >> 3;
    const int m0   = blockIdx.x * 128;

    for (int r = warp; r < 128; r += 8) {
        int m = m0 + r;
        float4 v = make_float4(0.f, 0.f, 0.f, 0.f);
        if (m < N_NODES)
            v = __ldg(reinterpret_cast<const float4*>(X + (size_t)m * FEAT) + lane);
        float* row = sX + r * PAD + lane * 4;
        row[0] = v.x; row[1] = v.y; row[2] = v.z; row[3] = v.w;
    }
    for (int n = warp; n < N_CLS; n += 8) {
        float4 v = __ldg(reinterpret_cast<const float4*>(Wc + (size_t)n * FEAT) + lane);
        float* row = sW + n * PAD + lane * 4;
        row[0] = v.x; row[1] = v.y; row[2] = v.z; row[3] = v.w;
    }
    __syncthreads();

    float acc[4][5];
#pragma unroll
    for (int r = 0; r < 4; r++)
#pragma unroll
        for (int c = 0; c < 5; c++) acc[r][c] = 0.f;

#pragma unroll 4
    for (int k = 0; k < 128; k++) {
        float a[4], w[5];
#pragma unroll
        for (int r = 0; r < 4; r++) a[r] = sX[(ty * 4 + r) * PAD + k];
#pragma unroll
        for (int c = 0; c < 5; c++) w[c] = sW[(tx + 8 * c) * PAD + k];
#pragma unroll
        for (int r = 0; r < 4; r++)
#pragma unroll
            for (int c = 0; c < 5; c++)
                acc[r][c] = fmaf(a[r], w[c], acc[r][c]);
    }

#pragma unroll
    for (int r = 0; r < 4; r++) {
        int m = m0 + ty * 4 + r;
        if (m < N_NODES) {
#pragma unroll
            for (int c = 0; c < 5; c++) {
                int n = tx + 8 * c;
                out[(size_t)m * N_CLS + n] = acc[r][c] + __ldg(bc + n);
            }
        }
    }
}

// ---------------- launch ----------------
extern "C" void kernel_launch(void* const* d_in, const int* in_sizes, int n_in,
                              void* d_out, int out_size) {
    const float* x   = (const float*)d_in[0];
    const int*   ei  = (const int*)d_in[1];
    const float* Wl1 = (const float*)d_in[2];
    const float* bl1 = (const float*)d_in[3];
    const float* Wr1 = (const float*)d_in[4];
    const float* Wl2 = (const float*)d_in[5];
    const float* bl2 = (const float*)d_in[6];
    const float* Wr2 = (const float*)d_in[7];
    const float* Wl3 = (const float*)d_in[8];
    const float* bl3 = (const float*)d_in[9];
    const float* Wr3 = (const float*)d_in[10];
    const float* Wc  = (const float*)d_in[11];
    const float* bc  = (const float*)d_in[12];
    float* out = (float*)d_out;

    const int* src = ei;
    const int* dst = ei + N_EDGES;

    float *p_agg, *p_h1, *p_h2, *p_h3;
    __nv_bfloat16* p_ws;
    cudaGetSymbolAddress((void**)&p_agg, g_agg);
    cudaGetSymbolAddress((void**)&p_h1,  g_h1);
    cudaGetSymbolAddress((void**)&p_h2,  g_h2);
    cudaGetSymbolAddress((void**)&p_h3,  g_h3);
    cudaGetSymbolAddress((void**)&p_ws,  g_wsplit);

    cudaFuncSetAttribute(sage_gemm_mma, cudaFuncAttributeMaxDynamicSharedMemorySize, SMEM_MMA);
    cudaFuncSetAttribute(classifier_k,  cudaFuncAttributeMaxDynamicSharedMemorySize, SMEM_CLS);

    const int edge_blocks   = (N_EDGES + 255) / 256;
    const int gather_blocks = (N_NODES * 32 + 255) / 256;
    const int gemm_blocks   = (N_NODES + 63) / 64;
    const int cls_blocks    = (N_NODES + 127) / 128;
    const size_t WSTRIDE = 2 * 2 * 16384;   // bf16 per layer

    // weight prep + CSR build (once)
    prep_weights<<<(3 * 2 * 16384 + 255) / 256, 256>>>(Wl1, Wr1, Wl2, Wr2, Wl3, Wr3);
    zero_degi<<<(N_NODES + 255) / 256, 256>>>();
    deg_count_i<<<edge_blocks, 256>>>(dst);
    scan_part<<<SCAN_BLOCKS, 256>>>();
    scan_top<<<1, 256>>>();
    scan_final<<<SCAN_BLOCKS, 256>>>();
    bucket_edges<<<edge_blocks, 256>>>(src, dst);

    // layer 1
    gather_mean<<<gather_blocks, 256>>>(x);
    sage_gemm_mma<<<gemm_blocks, 256, SMEM_MMA>>>(p_agg, x, p_ws + 0 * WSTRIDE, bl1, nullptr, p_h1);

    // layer 2
    gather_mean<<<gather_blocks, 256>>>(p_h1);
    sage_gemm_mma<<<gemm_blocks, 256, SMEM_MMA>>>(p_agg, p_h1, p_ws + 1 * WSTRIDE, bl2, nullptr, p_h2);

    // layer 3 + residual
    gather_mean<<<gather_blocks, 256>>>(p_h2);
    sage_gemm_mma<<<gemm_blocks, 256, SMEM_MMA>>>(p_agg, p_h2, p_ws + 2 * WSTRIDE, bl3, p_h2, p_h3);

    // classifier
    classifier_k<<<cls_blocks, 256, SMEM_CLS>>>(p_h3, Wc, bc, out);
}